// round 12
// baseline (speedup 1.0000x reference)
#include <cuda_runtime.h>
#include <cuda_bf16.h>
#include <cstdint>

#define NB 4
#define LL 8192
#define SSZ 8192
#define HH 8
#define DD 64
#define NH (NB * HH)
#define CHA 32           // s-chunks per (n,h); 256 s per chunk
#define PART_STRIDE 4160 // 4096 kv + 64 ksum
#define EPS 1e-6f
#define BR 72            // B rows: 64 kv^T + 1 ksum + 7 zero
#define BSTR 144         // bf16 row stride bytes (72 bf16)
#define SEL 72

typedef unsigned long long u64;
typedef unsigned int u32;

__device__ float g_part[NH * CHA * PART_STRIDE];
__device__ __nv_bfloat16 g_kvbf_hi[NH * BR * DD];
__device__ __nv_bfloat16 g_kvbf_lo[NH * BR * DD];

__device__ __forceinline__ float fmap(float x) {
    return x > 0.f ? x + 1.f : __expf(x);
}

__device__ __forceinline__ u32 smem_u32(const void* p) {
    u32 a;
    asm("{ .reg .u64 t; cvta.to.shared.u64 t, %1; cvt.u32.u64 %0, t; }"
        : "=r"(a) : "l"(p));
    return a;
}

__device__ __forceinline__ void cpasync16(u32 saddr, const void* gptr) {
    asm volatile("cp.async.cg.shared.global [%0], [%1], 16;"
                 :: "r"(saddr), "l"(gptr));
}
#define CP_COMMIT() asm volatile("cp.async.commit_group;" ::: "memory")
#define CP_WAIT1()  asm volatile("cp.async.wait_group 1;" ::: "memory")
#define CP_WAIT0()  asm volatile("cp.async.wait_group 0;" ::: "memory")

__device__ __forceinline__ void ldsm4(u32* r, u32 addr) {
    asm volatile("ldmatrix.sync.aligned.m8n8.x4.shared.b16 {%0,%1,%2,%3}, [%4];"
                 : "=r"(r[0]), "=r"(r[1]), "=r"(r[2]), "=r"(r[3]) : "r"(addr));
}
__device__ __forceinline__ void ldsm4t(u32* r, u32 addr) {
    asm volatile("ldmatrix.sync.aligned.m8n8.x4.trans.shared.b16 {%0,%1,%2,%3}, [%4];"
                 : "=r"(r[0]), "=r"(r[1]), "=r"(r[2]), "=r"(r[3]) : "r"(addr));
}
__device__ __forceinline__ void ldsm2(u32* r, u32 addr) {
    asm volatile("ldmatrix.sync.aligned.m8n8.x2.shared.b16 {%0,%1}, [%2];"
                 : "=r"(r[0]), "=r"(r[1]) : "r"(addr));
}
__device__ __forceinline__ void ldsm2t(u32* r, u32 addr) {
    asm volatile("ldmatrix.sync.aligned.m8n8.x2.trans.shared.b16 {%0,%1}, [%2];"
                 : "=r"(r[0]), "=r"(r[1]) : "r"(addr));
}

__device__ __forceinline__ void mma_bf16(float* c, const u32* a, u32 b0, u32 b1) {
    asm volatile(
        "mma.sync.aligned.m16n8k16.row.col.f32.bf16.bf16.f32 "
        "{%0,%1,%2,%3}, {%4,%5,%6,%7}, {%8,%9}, {%0,%1,%2,%3};"
        : "+f"(c[0]), "+f"(c[1]), "+f"(c[2]), "+f"(c[3])
        : "r"(a[0]), "r"(a[1]), "r"(a[2]), "r"(a[3]), "r"(b0), "r"(b1));
}

__device__ __forceinline__ unsigned short bfbits(float x) {
    __nv_bfloat16 b = __float2bfloat16_rn(x);
    return *(unsigned short*)&b;
}

__device__ __forceinline__ void split2(float f0, float f1, u32& hi, u32& lo) {
    unsigned short h0 = bfbits(f0), h1 = bfbits(f1);
    __nv_bfloat16 hv0 = *(__nv_bfloat16*)&h0, hv1 = *(__nv_bfloat16*)&h1;
    unsigned short l0 = bfbits(f0 - __bfloat162float(hv0));
    unsigned short l1 = bfbits(f1 - __bfloat162float(hv1));
    hi = (u32)h0 | ((u32)h1 << 16);
    lo = (u32)l0 | ((u32)l1 << 16);
}

// ================= Kernel A: HMMA kv partial, cp.async pipelined =================
// dynamic smem layout (bytes)
#define KV_KF32 0                       // 2 x 8192
#define KV_VF32 16384                   // 2 x 8192
#define KV_KHI  32768                   // 32*144 = 4608 each
#define KV_KLO  (32768 + 4608)
#define KV_VHI  (32768 + 9216)
#define KV_VLO  (32768 + 13824)
#define KV_SMEM_BYTES (32768 + 18432)   // 51200

__global__ __launch_bounds__(128) void kv_mma_kernel(
    const float* __restrict__ kin, const float* __restrict__ vin,
    const float* __restrict__ kv_mask)
{
    extern __shared__ char smem[];
    const u32 sb = smem_u32(smem);
    const u32 sb_khi = sb + KV_KHI, sb_klo = sb + KV_KLO;
    const u32 sb_vhi = sb + KV_VHI, sb_vlo = sb + KV_VLO;

    const int nh = blockIdx.x;
    const int n = nh >> 3, h = nh & 7;
    const int s0 = blockIdx.y * 256;
    const int t = threadIdx.x;
    const int lane = t & 31, w = t >> 5;

    // ones column for ksum (v cols 64-71), written once
    if (t < 32) {
        *(uint4*)(smem + KV_VHI + t * BSTR + 128) = make_uint4(0x3F80u, 0u, 0u, 0u);
        *(uint4*)(smem + KV_VLO + t * BSTR + 128) = make_uint4(0u, 0u, 0u, 0u);
    }

    const size_t gbase = (((size_t)n * SSZ + s0) * HH + h) * DD;

    // prologue: issue tile 0 (chunks c = t + j*128; row = c>>4, col16 = c&15)
    #pragma unroll
    for (int j = 0; j < 4; j++) {
        int c = t + j * 128;
        int r = c >> 4, c16 = c & 15;
        size_t g = gbase + (size_t)r * HH * DD + c16 * 4;
        cpasync16(sb + KV_KF32 + c * 16, kin + g);
        cpasync16(sb + KV_VF32 + c * 16, vin + g);
    }
    CP_COMMIT();

    float acc[9][4] = {};

    #pragma unroll 1
    for (int tile = 0; tile < 8; tile++) {
        const int buf = tile & 1;
        if (tile < 7) {
            const int nb = buf ^ 1;
            #pragma unroll
            for (int j = 0; j < 4; j++) {
                int c = t + j * 128;
                int r = c >> 4, c16 = c & 15;
                size_t g = gbase + (size_t)((tile + 1) * 32 + r) * HH * DD + c16 * 4;
                cpasync16(sb + KV_KF32 + nb * 8192 + c * 16, kin + g);
                cpasync16(sb + KV_VF32 + nb * 8192 + c * 16, vin + g);
            }
            CP_COMMIT();
            CP_WAIT1();
        } else {
            CP_WAIT0();
        }

        // convert own chunks (no barrier needed: same thread copied them)
        #pragma unroll
        for (int e = 0; e < 4; e++) {
            int idx = t + e * 128;
            int r = idx >> 4, c4 = (idx & 15) * 4;
            int s = s0 + tile * 32 + r;
            float m = kv_mask[n * SSZ + s];
            float4 kq = *(const float4*)(smem + KV_KF32 + buf * 8192 + idx * 16);
            float4 vq = *(const float4*)(smem + KV_VF32 + buf * 8192 + idx * 16);
            u32 kh0, kl0, kh1, kl1, vh0, vl0, vh1, vl1;
            split2(fmap(kq.x) * m, fmap(kq.y) * m, kh0, kl0);
            split2(fmap(kq.z) * m, fmap(kq.w) * m, kh1, kl1);
            split2(vq.x * m, vq.y * m, vh0, vl0);
            split2(vq.z * m, vq.w * m, vh1, vl1);
            u32 off = r * BSTR + c4 * 2;
            *(u32*)(smem + KV_KHI + off) = kh0; *(u32*)(smem + KV_KHI + off + 4) = kh1;
            *(u32*)(smem + KV_KLO + off) = kl0; *(u32*)(smem + KV_KLO + off + 4) = kl1;
            *(u32*)(smem + KV_VHI + off) = vh0; *(u32*)(smem + KV_VHI + off + 4) = vh1;
            *(u32*)(smem + KV_VLO + off) = vl0; *(u32*)(smem + KV_VLO + off + 4) = vl1;
        }
        __syncthreads();

        // MMA (identical fragment mapping to verified round-11 kernel)
        #pragma unroll
        for (int kk = 0; kk < 2; kk++) {
            u32 arow = (u32)((lane & 7) + ((lane >> 4) & 1) * 8 + kk * 16);
            u32 acol = (u32)(w * 16 + ((lane >> 3) & 1) * 8);
            u32 aoff = arow * BSTR + acol * 2;
            u32 ahi[4], alo[4];
            ldsm4t(ahi, sb_khi + aoff);
            ldsm4t(alo, sb_klo + aoff);

            u32 brow = (u32)((lane & 7) + ((lane >> 3) & 1) * 8 + kk * 16);
            #pragma unroll
            for (int p = 0; p < 4; p++) {
                u32 boff = brow * BSTR + (u32)(p * 16 + ((lane >> 4) & 1) * 8) * 2;
                u32 bh[4], bl[4];
                ldsm4t(bh, sb_vhi + boff);
                ldsm4t(bl, sb_vlo + boff);
                mma_bf16(acc[2 * p],     ahi, bh[0], bh[1]);
                mma_bf16(acc[2 * p],     ahi, bl[0], bl[1]);
                mma_bf16(acc[2 * p],     alo, bh[0], bh[1]);
                mma_bf16(acc[2 * p + 1], ahi, bh[2], bh[3]);
                mma_bf16(acc[2 * p + 1], ahi, bl[2], bl[3]);
                mma_bf16(acc[2 * p + 1], alo, bh[2], bh[3]);
            }
            {
                u32 b2off = brow * BSTR + 64 * 2;
                u32 bh[2], bl[2];
                ldsm2t(bh, sb_vhi + b2off);
                ldsm2t(bl, sb_vlo + b2off);
                mma_bf16(acc[8], ahi, bh[0], bh[1]);
                mma_bf16(acc[8], ahi, bl[0], bl[1]);
                mma_bf16(acc[8], alo, bh[0], bh[1]);
            }
        }
        __syncthreads();
    }

    float* part = &g_part[(nh * CHA + blockIdx.y) * PART_STRIDE];
    const int r0 = w * 16 + (lane >> 2);
    const int col = 2 * (lane & 3);
    #pragma unroll
    for (int nt = 0; nt < 8; nt++) {
        *(float2*)&part[r0 * 64 + nt * 8 + col] = make_float2(acc[nt][0], acc[nt][1]);
        *(float2*)&part[(r0 + 8) * 64 + nt * 8 + col] = make_float2(acc[nt][2], acc[nt][3]);
    }
    if ((lane & 3) == 0) {
        part[4096 + r0] = acc[8][0];
        part[4096 + r0 + 8] = acc[8][2];
    }
}

// ================= Reduce: fp32 sum -> transposed bf16 hi/lo =================
__global__ __launch_bounds__(256) void kv_reduce_kernel() {
    int idx = blockIdx.x * 256 + threadIdx.x;
    int nh = idx / PART_STRIDE;
    int el = idx - nh * PART_STRIDE;
    float s = 0.f;
    #pragma unroll 8
    for (int ch = 0; ch < CHA; ch++)
        s += g_part[(nh * CHA + ch) * PART_STRIDE + el];

    __nv_bfloat16 hi = __float2bfloat16_rn(s);
    __nv_bfloat16 lo = __float2bfloat16_rn(s - __bfloat162float(hi));

    int dst;
    if (el < 4096) {
        int d = el >> 6, v = el & 63;
        dst = nh * (BR * DD) + v * 64 + d;
    } else {
        int d = el - 4096;
        dst = nh * (BR * DD) + 64 * 64 + d;
    }
    g_kvbf_hi[dst] = hi;
    g_kvbf_lo[dst] = lo;
}

// ================= Kernel B: HMMA out, cp.async pipelined over 8 l-tiles =================
// dynamic smem layout (bytes)
#define O_QF32 0                        // 2 x 16384
#define O_AHI  32768                    // 64*144 = 9216
#define O_ALO  (32768 + 9216)
#define O_BHI  (32768 + 18432)          // 72*144 = 10368
#define O_BLO  (32768 + 18432 + 10368)
#define O_SMEM_BYTES (32768 + 18432 + 20736)   // 71936

__global__ __launch_bounds__(128) void out_mma_kernel(
    const float* __restrict__ qin, const float* __restrict__ q_mask,
    float* __restrict__ out)
{
    extern __shared__ char smem[];
    const u32 sb = smem_u32(smem);

    const int nh = blockIdx.x;
    const int n = nh >> 3, h = nh & 7;
    const int lbase = blockIdx.y * 512;
    const int t = threadIdx.x;
    const int lane = t & 31, w = t >> 5;

    // stage B once (72 rows x 64 bf16, hi/lo)
    {
        const u32* ghi = (const u32*)&g_kvbf_hi[nh * (BR * DD)];
        const u32* glo = (const u32*)&g_kvbf_lo[nh * (BR * DD)];
        #pragma unroll
        for (int e = 0; e < 18; e++) {
            int idx = t + e * 128;
            int row = idx >> 5, c = idx & 31;
            *(u32*)(smem + O_BHI + row * BSTR + c * 4) = ghi[idx];
            *(u32*)(smem + O_BLO + row * BSTR + c * 4) = glo[idx];
        }
    }

    const size_t gqbase = (((size_t)n * LL + lbase) * HH + h) * DD;

    // prologue: issue q tile 0 (64 rows; chunk c = t + j*128; row=c>>4, col16=c&15)
    #pragma unroll
    for (int j = 0; j < 8; j++) {
        int c = t + j * 128;
        int r = c >> 4, c16 = c & 15;
        cpasync16(sb + O_QF32 + c * 16,
                  qin + gqbase + (size_t)r * HH * DD + c16 * 4);
    }
    CP_COMMIT();

    // precomputed fragment offsets (identical mapping to verified round-10 kernel)
    const u32 a_frag = (u32)(w * 16 + (lane & 15)) * BSTR + (u32)(lane >> 4) * 16;
    const int bi = lane & 7, bg = lane >> 3;
    const u32 b4_off = (u32)(bi + ((bg & 2) << 2)) * BSTR + (u32)(bg & 1) * 16;
    const u32 b2_off = (u32)(64 + bi) * BSTR + (u32)(bg & 1) * 16;

    #pragma unroll 1
    for (int tile = 0; tile < 8; tile++) {
        const int buf = tile & 1;
        if (tile < 7) {
            const int nb = buf ^ 1;
            #pragma unroll
            for (int j = 0; j < 8; j++) {
                int c = t + j * 128;
                int r = c >> 4, c16 = c & 15;
                cpasync16(sb + O_QF32 + nb * 16384 + c * 16,
                          qin + gqbase + (size_t)((tile + 1) * 64 + r) * HH * DD + c16 * 4);
            }
            CP_COMMIT();
            CP_WAIT1();
        } else {
            CP_WAIT0();
        }

        // convert own chunks -> A hi/lo
        #pragma unroll
        for (int e = 0; e < 8; e++) {
            int idx = t + e * 128;
            int l = idx >> 4, c4 = (idx & 15) * 4;
            float m = q_mask[n * LL + lbase + tile * 64 + l];
            float4 x = *(const float4*)(smem + O_QF32 + buf * 16384 + idx * 16);
            u32 h0, lo0, h1, lo1;
            split2(fmap(x.x) * m, fmap(x.y) * m, h0, lo0);
            split2(fmap(x.z) * m, fmap(x.w) * m, h1, lo1);
            u32 off = l * BSTR + c4 * 2;
            *(u32*)(smem + O_AHI + off)     = h0;
            *(u32*)(smem + O_AHI + off + 4) = h1;
            *(u32*)(smem + O_ALO + off)     = lo0;
            *(u32*)(smem + O_ALO + off + 4) = lo1;
        }
        __syncthreads();

        float acc[9][4] = {};
        #pragma unroll
        for (int kk = 0; kk < 4; kk++) {
            const u32 koff = kk * 32;
            u32 ahi[4], alo[4];
            ldsm4(ahi, sb + O_AHI + a_frag + koff);
            ldsm4(alo, sb + O_ALO + a_frag + koff);

            #pragma unroll
            for (int p = 0; p < 4; p++) {
                u32 bh[4], bl[4];
                u32 ba = (u32)(p * 16) * BSTR + b4_off + koff;
                ldsm4(bh, sb + O_BHI + ba);
                ldsm4(bl, sb + O_BLO + ba);
                mma_bf16(acc[2 * p],     ahi, bh[0], bh[1]);
                mma_bf16(acc[2 * p],     ahi, bl[0], bl[1]);
                mma_bf16(acc[2 * p],     alo, bh[0], bh[1]);
                mma_bf16(acc[2 * p + 1], ahi, bh[2], bh[3]);
                mma_bf16(acc[2 * p + 1], ahi, bl[2], bl[3]);
                mma_bf16(acc[2 * p + 1], alo, bh[2], bh[3]);
            }
            {
                u32 bh[2], bl[2];
                ldsm2(bh, sb + O_BHI + b2_off + koff);
                ldsm2(bl, sb + O_BLO + b2_off + koff);
                mma_bf16(acc[8], ahi, bh[0], bh[1]);
                mma_bf16(acc[8], ahi, bl[0], bl[1]);
                mma_bf16(acc[8], alo, bh[0], bh[1]);
            }
        }

        // epilogue for this tile
        float n0 = __shfl_sync(0xffffffffu, acc[8][0], lane & ~3);
        float n1 = __shfl_sync(0xffffffffu, acc[8][2], lane & ~3);
        float dv0 = 1.f / (n0 + EPS);
        float dv1 = 1.f / (n1 + EPS);

        const int l = lbase + tile * 64 + w * 16 + (lane >> 2);
        const int col = 2 * (lane & 3);
        size_t g0 = (((size_t)n * LL + l) * HH + h) * DD;
        size_t g1 = g0 + (size_t)8 * HH * DD;
        #pragma unroll
        for (int nt = 0; nt < 8; nt++) {
            *(float2*)&out[g0 + nt * 8 + col] =
                make_float2(acc[nt][0] * dv0, acc[nt][1] * dv0);
            *(float2*)&out[g1 + nt * 8 + col] =
                make_float2(acc[nt][2] * dv1, acc[nt][3] * dv1);
        }
        __syncthreads();
    }
}

extern "C" void kernel_launch(void* const* d_in, const int* in_sizes, int n_in,
                              void* d_out, int out_size)
{
    const float* q   = (const float*)d_in[0];
    const float* k   = (const float*)d_in[1];
    const float* v   = (const float*)d_in[2];
    const float* qm  = (const float*)d_in[3];
    const float* kvm = (const float*)d_in[4];
    float* out = (float*)d_out;

    static bool attr_done = false;
    if (!attr_done) {
        cudaFuncSetAttribute(kv_mma_kernel,
                             cudaFuncAttributeMaxDynamicSharedMemorySize,
                             KV_SMEM_BYTES);
        cudaFuncSetAttribute(out_mma_kernel,
                             cudaFuncAttributeMaxDynamicSharedMemorySize,
                             O_SMEM_BYTES);
        attr_done = true;
    }

    kv_mma_kernel<<<dim3(NH, CHA), 128, KV_SMEM_BYTES>>>(k, v, kvm);
    kv_reduce_kernel<<<(NH * PART_STRIDE) / 256, 256>>>();
    out_mma_kernel<<<dim3(NH, 16), 128, O_SMEM_BYTES>>>(q, qm, out);
}

// round 13
// speedup vs baseline: 1.2542x; 1.2542x over previous
#include <cuda_runtime.h>
#include <cuda_bf16.h>
#include <cstdint>

#define NB 4
#define LL 8192
#define SSZ 8192
#define HH 8
#define DD 64
#define NH (NB * HH)
#define CHA 32           // s-chunks per (n,h); 256 s per chunk
#define PART_STRIDE 4160 // 4096 kv + 64 ksum
#define EPS 1e-6f
#define BR 72            // B rows: 64 kv^T + 1 ksum + 7 zero
#define BSTR 144         // bf16 row stride bytes (72 bf16)

typedef unsigned long long u64;
typedef unsigned int u32;

__device__ float g_part[NH * CHA * PART_STRIDE];
__device__ __nv_bfloat16 g_kvbf_hi[NH * BR * DD];
__device__ __nv_bfloat16 g_kvbf_lo[NH * BR * DD];

__device__ __forceinline__ float fmap(float x) {
    return x > 0.f ? x + 1.f : __expf(x);
}

__device__ __forceinline__ u32 smem_u32(const void* p) {
    u32 a;
    asm("{ .reg .u64 t; cvta.to.shared.u64 t, %1; cvt.u32.u64 %0, t; }"
        : "=r"(a) : "l"(p));
    return a;
}

__device__ __forceinline__ void cpasync16(u32 saddr, const void* gptr) {
    asm volatile("cp.async.cg.shared.global [%0], [%1], 16;"
                 :: "r"(saddr), "l"(gptr));
}
#define CP_COMMIT() asm volatile("cp.async.commit_group;" ::: "memory")
#define CP_WAIT1()  asm volatile("cp.async.wait_group 1;" ::: "memory")
#define CP_WAIT0()  asm volatile("cp.async.wait_group 0;" ::: "memory")

__device__ __forceinline__ void ldsm4(u32* r, u32 addr) {
    asm volatile("ldmatrix.sync.aligned.m8n8.x4.shared.b16 {%0,%1,%2,%3}, [%4];"
                 : "=r"(r[0]), "=r"(r[1]), "=r"(r[2]), "=r"(r[3]) : "r"(addr));
}
__device__ __forceinline__ void ldsm4t(u32* r, u32 addr) {
    asm volatile("ldmatrix.sync.aligned.m8n8.x4.trans.shared.b16 {%0,%1,%2,%3}, [%4];"
                 : "=r"(r[0]), "=r"(r[1]), "=r"(r[2]), "=r"(r[3]) : "r"(addr));
}
__device__ __forceinline__ void ldsm2(u32* r, u32 addr) {
    asm volatile("ldmatrix.sync.aligned.m8n8.x2.shared.b16 {%0,%1}, [%2];"
                 : "=r"(r[0]), "=r"(r[1]) : "r"(addr));
}
__device__ __forceinline__ void ldsm2t(u32* r, u32 addr) {
    asm volatile("ldmatrix.sync.aligned.m8n8.x2.trans.shared.b16 {%0,%1}, [%2];"
                 : "=r"(r[0]), "=r"(r[1]) : "r"(addr));
}

__device__ __forceinline__ void mma_bf16(float* c, const u32* a, u32 b0, u32 b1) {
    asm volatile(
        "mma.sync.aligned.m16n8k16.row.col.f32.bf16.bf16.f32 "
        "{%0,%1,%2,%3}, {%4,%5,%6,%7}, {%8,%9}, {%0,%1,%2,%3};"
        : "+f"(c[0]), "+f"(c[1]), "+f"(c[2]), "+f"(c[3])
        : "r"(a[0]), "r"(a[1]), "r"(a[2]), "r"(a[3]), "r"(b0), "r"(b1));
}

__device__ __forceinline__ unsigned short bfbits(float x) {
    __nv_bfloat16 b = __float2bfloat16_rn(x);
    return *(unsigned short*)&b;
}

__device__ __forceinline__ void split2(float f0, float f1, u32& hi, u32& lo) {
    unsigned short h0 = bfbits(f0), h1 = bfbits(f1);
    __nv_bfloat16 hv0 = *(__nv_bfloat16*)&h0, hv1 = *(__nv_bfloat16*)&h1;
    unsigned short l0 = bfbits(f0 - __bfloat162float(hv0));
    unsigned short l1 = bfbits(f1 - __bfloat162float(hv1));
    hi = (u32)h0 | ((u32)h1 << 16);
    lo = (u32)l0 | ((u32)l1 << 16);
}

// ================= Kernel A: HMMA kv partial, cp.async pipelined (round-12, 53.8us) =================
#define KV_KF32 0                       // 2 x 8192
#define KV_VF32 16384                   // 2 x 8192
#define KV_KHI  32768                   // 32*144 = 4608 each
#define KV_KLO  (32768 + 4608)
#define KV_VHI  (32768 + 9216)
#define KV_VLO  (32768 + 13824)
#define KV_SMEM_BYTES (32768 + 18432)   // 51200

__global__ __launch_bounds__(128) void kv_mma_kernel(
    const float* __restrict__ kin, const float* __restrict__ vin,
    const float* __restrict__ kv_mask)
{
    extern __shared__ char smem[];
    const u32 sb = smem_u32(smem);
    const u32 sb_khi = sb + KV_KHI, sb_klo = sb + KV_KLO;
    const u32 sb_vhi = sb + KV_VHI, sb_vlo = sb + KV_VLO;

    const int nh = blockIdx.x;
    const int n = nh >> 3, h = nh & 7;
    const int s0 = blockIdx.y * 256;
    const int t = threadIdx.x;
    const int lane = t & 31, w = t >> 5;

    if (t < 32) {
        *(uint4*)(smem + KV_VHI + t * BSTR + 128) = make_uint4(0x3F80u, 0u, 0u, 0u);
        *(uint4*)(smem + KV_VLO + t * BSTR + 128) = make_uint4(0u, 0u, 0u, 0u);
    }

    const size_t gbase = (((size_t)n * SSZ + s0) * HH + h) * DD;

    #pragma unroll
    for (int j = 0; j < 4; j++) {
        int c = t + j * 128;
        int r = c >> 4, c16 = c & 15;
        size_t g = gbase + (size_t)r * HH * DD + c16 * 4;
        cpasync16(sb + KV_KF32 + c * 16, kin + g);
        cpasync16(sb + KV_VF32 + c * 16, vin + g);
    }
    CP_COMMIT();

    float acc[9][4] = {};

    #pragma unroll 1
    for (int tile = 0; tile < 8; tile++) {
        const int buf = tile & 1;
        if (tile < 7) {
            const int nb = buf ^ 1;
            #pragma unroll
            for (int j = 0; j < 4; j++) {
                int c = t + j * 128;
                int r = c >> 4, c16 = c & 15;
                size_t g = gbase + (size_t)((tile + 1) * 32 + r) * HH * DD + c16 * 4;
                cpasync16(sb + KV_KF32 + nb * 8192 + c * 16, kin + g);
                cpasync16(sb + KV_VF32 + nb * 8192 + c * 16, vin + g);
            }
            CP_COMMIT();
            CP_WAIT1();
        } else {
            CP_WAIT0();
        }

        #pragma unroll
        for (int e = 0; e < 4; e++) {
            int idx = t + e * 128;
            int r = idx >> 4, c4 = (idx & 15) * 4;
            int s = s0 + tile * 32 + r;
            float m = kv_mask[n * SSZ + s];
            float4 kq = *(const float4*)(smem + KV_KF32 + buf * 8192 + idx * 16);
            float4 vq = *(const float4*)(smem + KV_VF32 + buf * 8192 + idx * 16);
            u32 kh0, kl0, kh1, kl1, vh0, vl0, vh1, vl1;
            split2(fmap(kq.x) * m, fmap(kq.y) * m, kh0, kl0);
            split2(fmap(kq.z) * m, fmap(kq.w) * m, kh1, kl1);
            split2(vq.x * m, vq.y * m, vh0, vl0);
            split2(vq.z * m, vq.w * m, vh1, vl1);
            u32 off = r * BSTR + c4 * 2;
            *(u32*)(smem + KV_KHI + off) = kh0; *(u32*)(smem + KV_KHI + off + 4) = kh1;
            *(u32*)(smem + KV_KLO + off) = kl0; *(u32*)(smem + KV_KLO + off + 4) = kl1;
            *(u32*)(smem + KV_VHI + off) = vh0; *(u32*)(smem + KV_VHI + off + 4) = vh1;
            *(u32*)(smem + KV_VLO + off) = vl0; *(u32*)(smem + KV_VLO + off + 4) = vl1;
        }
        __syncthreads();

        #pragma unroll
        for (int kk = 0; kk < 2; kk++) {
            u32 arow = (u32)((lane & 7) + ((lane >> 4) & 1) * 8 + kk * 16);
            u32 acol = (u32)(w * 16 + ((lane >> 3) & 1) * 8);
            u32 aoff = arow * BSTR + acol * 2;
            u32 ahi[4], alo[4];
            ldsm4t(ahi, sb_khi + aoff);
            ldsm4t(alo, sb_klo + aoff);

            u32 brow = (u32)((lane & 7) + ((lane >> 3) & 1) * 8 + kk * 16);
            #pragma unroll
            for (int p = 0; p < 4; p++) {
                u32 boff = brow * BSTR + (u32)(p * 16 + ((lane >> 4) & 1) * 8) * 2;
                u32 bh[4], bl[4];
                ldsm4t(bh, sb_vhi + boff);
                ldsm4t(bl, sb_vlo + boff);
                mma_bf16(acc[2 * p],     ahi, bh[0], bh[1]);
                mma_bf16(acc[2 * p],     ahi, bl[0], bl[1]);
                mma_bf16(acc[2 * p],     alo, bh[0], bh[1]);
                mma_bf16(acc[2 * p + 1], ahi, bh[2], bh[3]);
                mma_bf16(acc[2 * p + 1], ahi, bl[2], bl[3]);
                mma_bf16(acc[2 * p + 1], alo, bh[2], bh[3]);
            }
            {
                u32 b2off = brow * BSTR + 64 * 2;
                u32 bh[2], bl[2];
                ldsm2t(bh, sb_vhi + b2off);
                ldsm2t(bl, sb_vlo + b2off);
                mma_bf16(acc[8], ahi, bh[0], bh[1]);
                mma_bf16(acc[8], ahi, bl[0], bl[1]);
                mma_bf16(acc[8], alo, bh[0], bh[1]);
            }
        }
        __syncthreads();
    }

    float* part = &g_part[(nh * CHA + blockIdx.y) * PART_STRIDE];
    const int r0 = w * 16 + (lane >> 2);
    const int col = 2 * (lane & 3);
    #pragma unroll
    for (int nt = 0; nt < 8; nt++) {
        *(float2*)&part[r0 * 64 + nt * 8 + col] = make_float2(acc[nt][0], acc[nt][1]);
        *(float2*)&part[(r0 + 8) * 64 + nt * 8 + col] = make_float2(acc[nt][2], acc[nt][3]);
    }
    if ((lane & 3) == 0) {
        part[4096 + r0] = acc[8][0];
        part[4096 + r0 + 8] = acc[8][2];
    }
}

// ================= Reduce: fp32 sum -> transposed bf16 hi/lo =================
__global__ __launch_bounds__(256) void kv_reduce_kernel() {
    int idx = blockIdx.x * 256 + threadIdx.x;
    int nh = idx / PART_STRIDE;
    int el = idx - nh * PART_STRIDE;
    float s = 0.f;
    #pragma unroll 8
    for (int ch = 0; ch < CHA; ch++)
        s += g_part[(nh * CHA + ch) * PART_STRIDE + el];

    __nv_bfloat16 hi = __float2bfloat16_rn(s);
    __nv_bfloat16 lo = __float2bfloat16_rn(s - __bfloat162float(hi));

    int dst;
    if (el < 4096) {
        int d = el >> 6, v = el & 63;
        dst = nh * (BR * DD) + v * 64 + d;
    } else {
        int d = el - 4096;
        dst = nh * (BR * DD) + 64 * 64 + d;
    }
    g_kvbf_hi[dst] = hi;
    g_kvbf_lo[dst] = lo;
}

// ================= Kernel B: HMMA out (round-10 verified, ~55us) =================
#define SM_AHI 0
#define SM_ALO (128 * BSTR)
#define SM_BHI (2 * 128 * BSTR)
#define SM_BLO (SM_BHI + BR * BSTR)
#define OUT_SMEM_BYTES (SM_BLO + BR * BSTR)   // 57600

__global__ __launch_bounds__(256) void out_mma_kernel(
    const float* __restrict__ qin, const float* __restrict__ q_mask,
    float* __restrict__ out)
{
    extern __shared__ char smem[];
    const u32 sb = smem_u32(smem);

    const int nh = blockIdx.x;
    const int n = nh >> 3, h = nh & 7;
    const int l0 = blockIdx.y * 128;
    const int t = threadIdx.x;
    const int lane = t & 31, w = t >> 5;

    {
        const u32* ghi = (const u32*)&g_kvbf_hi[nh * (BR * DD)];
        const u32* glo = (const u32*)&g_kvbf_lo[nh * (BR * DD)];
        #pragma unroll
        for (int e = 0; e < 9; e++) {
            int idx = t + e * 256;
            int row = idx >> 5, c = idx & 31;
            *(u32*)(smem + SM_BHI + row * BSTR + c * 4) = ghi[idx];
            *(u32*)(smem + SM_BLO + row * BSTR + c * 4) = glo[idx];
        }
    }

    #pragma unroll
    for (int e = 0; e < 8; e++) {
        int idx = t + e * 256;
        int l = idx >> 4, c4 = (idx & 15) * 4;
        float m = q_mask[n * LL + l0 + l];
        size_t g = (((size_t)(n * LL + l0 + l)) * HH + h) * DD + c4;
        float4 x = *(const float4*)&qin[g];
        u32 h0, lo0, h1, lo1;
        split2(fmap(x.x) * m, fmap(x.y) * m, h0, lo0);
        split2(fmap(x.z) * m, fmap(x.w) * m, h1, lo1);
        u32 off = l * BSTR + c4 * 2;
        *(u32*)(smem + SM_AHI + off)     = h0;
        *(u32*)(smem + SM_AHI + off + 4) = h1;
        *(u32*)(smem + SM_ALO + off)     = lo0;
        *(u32*)(smem + SM_ALO + off + 4) = lo1;
    }
    __syncthreads();

    const int mbase = w * 16;
    float acc[9][4] = {};

    const u32 a_off = (u32)(mbase + (lane & 15)) * BSTR + (u32)(lane >> 4) * 16;
    const int bi = lane & 7, bg = lane >> 3;
    const u32 b4_off = (u32)(bi + ((bg & 2) << 2)) * BSTR + (u32)(bg & 1) * 16;
    const u32 b2_off = (u32)(64 + bi) * BSTR + (u32)(bg & 1) * 16;

    #pragma unroll
    for (int kk = 0; kk < 4; kk++) {
        const u32 koff = kk * 32;
        u32 ahi[4], alo[4];
        ldsm4(ahi, sb + SM_AHI + a_off + koff);
        ldsm4(alo, sb + SM_ALO + a_off + koff);

        #pragma unroll
        for (int p = 0; p < 4; p++) {
            u32 bh[4], bl[4];
            u32 ba = (u32)(p * 16) * BSTR + b4_off + koff;
            ldsm4(bh, sb + SM_BHI + ba);
            ldsm4(bl, sb + SM_BLO + ba);
            mma_bf16(acc[2 * p],     ahi, bh[0], bh[1]);
            mma_bf16(acc[2 * p],     ahi, bl[0], bl[1]);
            mma_bf16(acc[2 * p],     alo, bh[0], bh[1]);
            mma_bf16(acc[2 * p + 1], ahi, bh[2], bh[3]);
            mma_bf16(acc[2 * p + 1], ahi, bl[2], bl[3]);
            mma_bf16(acc[2 * p + 1], alo, bh[2], bh[3]);
        }
        {
            u32 bh[2], bl[2];
            ldsm2(bh, sb + SM_BHI + b2_off + koff);
            ldsm2(bl, sb + SM_BLO + b2_off + koff);
            mma_bf16(acc[8], ahi, bh[0], bh[1]);
            mma_bf16(acc[8], ahi, bl[0], bl[1]);
            mma_bf16(acc[8], alo, bh[0], bh[1]);
        }
    }

    float n0 = __shfl_sync(0xffffffffu, acc[8][0], lane & ~3);
    float n1 = __shfl_sync(0xffffffffu, acc[8][2], lane & ~3);
    float dv0 = 1.f / (n0 + EPS);
    float dv1 = 1.f / (n1 + EPS);

    const int r0 = l0 + mbase + (lane >> 2);
    const int col = 2 * (lane & 3);
    size_t g0 = (((size_t)(n * LL + r0)) * HH + h) * DD;
    size_t g1 = g0 + (size_t)8 * HH * DD;

    #pragma unroll
    for (int nt = 0; nt < 8; nt++) {
        *(float2*)&out[g0 + nt * 8 + col] =
            make_float2(acc[nt][0] * dv0, acc[nt][1] * dv0);
        *(float2*)&out[g1 + nt * 8 + col] =
            make_float2(acc[nt][2] * dv1, acc[nt][3] * dv1);
    }
}

extern "C" void kernel_launch(void* const* d_in, const int* in_sizes, int n_in,
                              void* d_out, int out_size)
{
    const float* q   = (const float*)d_in[0];
    const float* k   = (const float*)d_in[1];
    const float* v   = (const float*)d_in[2];
    const float* qm  = (const float*)d_in[3];
    const float* kvm = (const float*)d_in[4];
    float* out = (float*)d_out;

    static bool attr_done = false;
    if (!attr_done) {
        cudaFuncSetAttribute(kv_mma_kernel,
                             cudaFuncAttributeMaxDynamicSharedMemorySize,
                             KV_SMEM_BYTES);
        cudaFuncSetAttribute(out_mma_kernel,
                             cudaFuncAttributeMaxDynamicSharedMemorySize,
                             OUT_SMEM_BYTES);
        attr_done = true;
    }

    kv_mma_kernel<<<dim3(NH, CHA), 128, KV_SMEM_BYTES>>>(k, v, kvm);
    kv_reduce_kernel<<<(NH * PART_STRIDE) / 256, 256>>>();
    out_mma_kernel<<<dim3(NH, 64), 256, OUT_SMEM_BYTES>>>(q, qm, out);
}